// round 12
// baseline (speedup 1.0000x reference)
#include <cuda_runtime.h>
#include <cuda_bf16.h>
#include <math.h>

#define OUT_G 12
#define V_G (OUT_G * OUT_G * OUT_G)   // 1728
#define MAXN 256
#define MAXC 64
#define NB 16                          // spatial bins per dim
#define NBINS (NB * NB * NB)           // 4096
#define NWMAX 4                        // uint64 mask words (up to 256 rois)
#define DOM_LO (-12.0f)
#define DOM_HI (12.0f)
#define CELL ((DOM_HI - DOM_LO) / (float)NB)   // 1.5

// Scratch (__device__ globals: allocation-free rule).
// g_scratch invariant: all-zero at kernel_launch entry (BSS gives the base
// case; finalize resets every chunk it consumed). g_count zeroed by setup.
__device__ unsigned g_scratch[MAXN * V_G * MAXC];
__device__ int g_count[MAXN * V_G];
__device__ unsigned long long g_mask[NBINS * NWMAX];
__device__ float g_roi[MAXN * 12];     // cx,cy,czc,cosa,sina,hx,hy,hz,vx,vy,vz,rad2

__device__ __forceinline__ unsigned enc_f(float f) {
    unsigned u = __float_as_uint(f);
    return (u & 0x80000000u) ? ~u : (u | 0x80000000u);
}
__device__ __forceinline__ float dec_f(unsigned u) {
    return (u & 0x80000000u) ? __uint_as_float(u & 0x7FFFFFFFu) : __uint_as_float(~u);
}

// ---------------------------------------------------------------------------
// Kernel 1: zero counts + roi params (block 0) + ballot-parallel bin masks.
// AABB uses the xy circumradius (conservative superset -> still correct; the
// exact in-box test in the points kernel decides membership).
// ---------------------------------------------------------------------------
__global__ void roi_setup_kernel(const float* __restrict__ rois, int N) {
    // Per-block: trig-free conservative AABB into smem.
    __shared__ float s_aabb[MAXN * 6];
    for (int r = threadIdx.x; r < N; r += blockDim.x) {
        float cx = __ldg(&rois[7 * r + 0]);
        float cy = __ldg(&rois[7 * r + 1]);
        float czb = __ldg(&rois[7 * r + 2]);
        float dx = __ldg(&rois[7 * r + 3]);
        float dy = __ldg(&rois[7 * r + 4]);
        float dz = __ldg(&rois[7 * r + 5]);
        float hx = dx * 0.5f, hy = dy * 0.5f, hz = dz * 0.5f;
        float czc = czb + dz * 0.5f;
        float rad = sqrtf(hx * hx + hy * hy);
        float* A = &s_aabb[r * 6];
        A[0] = cx - rad; A[1] = cx + rad;
        A[2] = cy - rad; A[3] = cy + rad;
        A[4] = czc - hz; A[5] = czc + hz;
    }
    // Block 0: exact roi params (the only sincos in the pipeline).
    if (blockIdx.x == 0) {
        for (int r = threadIdx.x; r < N; r += blockDim.x) {
            float cx = __ldg(&rois[7 * r + 0]);
            float cy = __ldg(&rois[7 * r + 1]);
            float czb = __ldg(&rois[7 * r + 2]);
            float dx = __ldg(&rois[7 * r + 3]);
            float dy = __ldg(&rois[7 * r + 4]);
            float dz = __ldg(&rois[7 * r + 5]);
            float rz = __ldg(&rois[7 * r + 6]);
            float czc = czb + dz * 0.5f;
            float cosa = cosf(-rz);
            float sina = sinf(-rz);
            float hx = dx * 0.5f, hy = dy * 0.5f, hz = dz * 0.5f;
            float* R = &g_roi[r * 12];
            R[0] = cx; R[1] = cy; R[2] = czc; R[3] = cosa; R[4] = sina;
            R[5] = hx; R[6] = hy; R[7] = hz;
            R[8] = dx / (float)OUT_G; R[9] = dy / (float)OUT_G; R[10] = dz / (float)OUT_G;
            R[11] = hx * hx + hy * hy;
        }
    }
    __syncthreads();

    int tid = blockIdx.x * blockDim.x + threadIdx.x;
    int nth = gridDim.x * blockDim.x;

    long nc = (long)N * V_G;
    for (long i = tid; i < nc; i += nth) g_count[i] = 0;

    // Ballot mask build: one lane per (bin, roi) test.
    int lane = threadIdx.x & 31;
    int gwarp = tid >> 5;
    int nwarps = nth >> 5;
    int nw32 = (N + 31) >> 5;                 // 32-bit words per bin
    int pairs = NBINS * nw32;
    unsigned* mask32 = reinterpret_cast<unsigned*>(g_mask);

    for (int idx = gwarp; idx < pairs; idx += nwarps) {
        int b = idx / nw32;
        int w32 = idx - b * nw32;
        int r = (w32 << 5) + lane;

        int bx = b & (NB - 1), by = (b >> 4) & (NB - 1), bz = b >> 8;
        float x0 = (bx == 0)      ? -3e38f : DOM_LO + bx * CELL;
        float x1 = (bx == NB - 1) ?  3e38f : DOM_LO + (bx + 1) * CELL;
        float y0 = (by == 0)      ? -3e38f : DOM_LO + by * CELL;
        float y1 = (by == NB - 1) ?  3e38f : DOM_LO + (by + 1) * CELL;
        float z0 = (bz == 0)      ? -3e38f : DOM_LO + bz * CELL;
        float z1 = (bz == NB - 1) ?  3e38f : DOM_LO + (bz + 1) * CELL;

        bool ov = false;
        if (r < N) {
            const float* A = &s_aabb[r * 6];
            ov = (A[0] <= x1) & (A[1] >= x0) &
                 (A[2] <= y1) & (A[3] >= y0) &
                 (A[4] <= z1) & (A[5] >= z0);
        }
        unsigned m = __ballot_sync(0xFFFFFFFFu, ov);
        if (lane == 0)
            mask32[b * (NWMAX * 2) + w32] = m;   // little-endian halves of uint64
        // zero the remaining 32-bit words for this bin once (w32 == 0 warp)
        if (w32 == 0 && lane == 0) {
            for (int w = nw32; w < NWMAX * 2; w++)
                mask32[b * (NWMAX * 2) + w] = 0u;
        }
    }
}

// ---------------------------------------------------------------------------
// Kernel 2: one thread per point. Params from g_roi -> smem. Bin lookup ->
// exact test only on mask bits. Atomics into scratch (fire-and-forget).
// ---------------------------------------------------------------------------
__global__ void roi_points_kernel(const float* __restrict__ pts,
                                  const float* __restrict__ feat,
                                  const int* __restrict__ mode_p,
                                  int N, int P, int C) {
    __shared__ float s_roi[MAXN * 12];
    int nfl = N * 12;
    for (int i = threadIdx.x; i < nfl; i += blockDim.x)
        s_roi[i] = g_roi[i];
    __syncthreads();

    int p = blockIdx.x * blockDim.x + threadIdx.x;
    if (p >= P) return;

    float px = __ldg(&pts[3 * p + 0]);
    float py = __ldg(&pts[3 * p + 1]);
    float pz = __ldg(&pts[3 * p + 2]);

    const float invcell = 1.0f / CELL;
    int bx = min(NB - 1, max(0, (int)((px - DOM_LO) * invcell)));
    int by = min(NB - 1, max(0, (int)((py - DOM_LO) * invcell)));
    int bz = min(NB - 1, max(0, (int)((pz - DOM_LO) * invcell)));
    int bin = (bz * NB + by) * NB + bx;

    int nw = (N + 63) >> 6;
    int mode = __ldg(mode_p);

    for (int w = 0; w < nw; w++) {
        unsigned long long m = __ldg(&g_mask[(long)bin * NWMAX + w]);
        while (m) {
            int bit = __ffsll((long long)m) - 1;
            m &= m - 1;
            int r = (w << 6) + bit;
            const float* R = &s_roi[r * 12];

            float lz = pz - R[2];
            float hz = R[7];
            if (fabsf(lz) > hz) continue;
            float sx = px - R[0];
            float sy = py - R[1];
            if (sx * sx + sy * sy > R[11]) continue;
            float cosa = R[3], sina = R[4];
            float lx = sx * cosa - sy * sina;
            float ly = sx * sina + sy * cosa;
            float hx = R[5], hy = R[6];
            if (fabsf(lx) >= hx) continue;
            if (fabsf(ly) >= hy) continue;

            int xi = min(max((int)floorf((lx + hx) / R[8]), 0), OUT_G - 1);
            int yi = min(max((int)floorf((ly + hy) / R[9]), 0), OUT_G - 1);
            int zi = min(max((int)floorf((lz + hz) / R[10]), 0), OUT_G - 1);
            int rv = r * V_G + (xi * OUT_G + yi) * OUT_G + zi;

            atomicAdd(&g_count[rv], 1);          // fire-and-forget -> REDG
            long base = (long)rv * C;

            if ((C & 3) == 0) {
                const float4* fp4 = (const float4*)(feat + (long)p * C);
                if (mode == 0) {
                    unsigned* o = g_scratch + base;
                    for (int c4 = 0; c4 < (C >> 2); c4++) {
                        float4 f = __ldg(fp4 + c4);
                        atomicMax(o + 4 * c4 + 0, enc_f(f.x));
                        atomicMax(o + 4 * c4 + 1, enc_f(f.y));
                        atomicMax(o + 4 * c4 + 2, enc_f(f.z));
                        atomicMax(o + 4 * c4 + 3, enc_f(f.w));
                    }
                } else {
                    float* o = reinterpret_cast<float*>(g_scratch) + base;
                    for (int c4 = 0; c4 < (C >> 2); c4++) {
                        float4 f = __ldg(fp4 + c4);
                        atomicAdd(o + 4 * c4 + 0, f.x);
                        atomicAdd(o + 4 * c4 + 1, f.y);
                        atomicAdd(o + 4 * c4 + 2, f.z);
                        atomicAdd(o + 4 * c4 + 3, f.w);
                    }
                }
            } else {
                const float* fp = feat + (long)p * C;
                if (mode == 0) {
                    unsigned* o = g_scratch + base;
                    for (int c = 0; c < C; c++) atomicMax(o + c, enc_f(__ldg(fp + c)));
                } else {
                    float* o = reinterpret_cast<float*>(g_scratch) + base;
                    for (int c = 0; c < C; c++) atomicAdd(o + c, __ldg(fp + c));
                }
            }
        }
    }
}

// ---------------------------------------------------------------------------
// Kernel 3a: finalize (C % 4 == 0). One thread per float4 chunk, coalesced.
// Empty voxels write 0 without touching scratch. Occupied: decode/divide,
// reset own scratch chunk (race-free), write out.
// ---------------------------------------------------------------------------
__global__ void roi_finalize_vec_kernel(const int* __restrict__ mode_p,
                                        float* __restrict__ out,
                                        int c4pv, int total4) {
    int i = blockIdx.x * blockDim.x + threadIdx.x;
    if (i >= total4) return;
    int v = i / c4pv;
    int cnt = __ldg(&g_count[v]);
    float4 f = make_float4(0.f, 0.f, 0.f, 0.f);
    if (cnt > 0) {
        uint4* s4 = reinterpret_cast<uint4*>(g_scratch) + i;
        uint4 s = *s4;
        if (__ldg(mode_p) == 0) {
            f.x = dec_f(s.x); f.y = dec_f(s.y);
            f.z = dec_f(s.z); f.w = dec_f(s.w);
        } else {
            float inv = 1.0f / (float)cnt;
            f.x = __uint_as_float(s.x) * inv;
            f.y = __uint_as_float(s.y) * inv;
            f.z = __uint_as_float(s.z) * inv;
            f.w = __uint_as_float(s.w) * inv;
        }
        *s4 = make_uint4(0u, 0u, 0u, 0u);   // restore invariant
    }
    reinterpret_cast<float4*>(out)[i] = f;
}

// ---------------------------------------------------------------------------
// Kernel 3b: generic finalize, one thread per element.
// ---------------------------------------------------------------------------
__global__ void roi_finalize_gen_kernel(const int* __restrict__ mode_p,
                                        float* __restrict__ out,
                                        int C, long total) {
    long i = (long)blockIdx.x * blockDim.x + threadIdx.x;
    if (i >= total) return;
    int v = (int)(i / C);
    int cnt = __ldg(&g_count[v]);
    float f = 0.0f;
    if (cnt > 0) {
        unsigned s = g_scratch[i];
        if (__ldg(mode_p) == 0) f = dec_f(s);
        else f = __uint_as_float(s) / (float)cnt;
        g_scratch[i] = 0u;
    }
    out[i] = f;
}

extern "C" void kernel_launch(void* const* d_in, const int* in_sizes, int n_in,
                              void* d_out, int out_size) {
    const float* rois = (const float*)d_in[0];
    const float* pts = (const float*)d_in[1];
    const float* feat = (const float*)d_in[2];
    const int* mode_p = (const int*)d_in[3];
    float* out = (float*)d_out;

    int N = in_sizes[0] / 7;          // 64
    int P = in_sizes[1] / 3;          // 100000
    int C = in_sizes[2] / P;          // 16
    long total_out = (long)out_size;  // N*V*C

    roi_setup_kernel<<<512, 256>>>(rois, N);
    roi_points_kernel<<<(P + 255) / 256, 256>>>(pts, feat, mode_p, N, P, C);

    if ((C & 3) == 0) {
        int c4pv = C >> 2;
        int total4 = (int)(total_out >> 2);
        roi_finalize_vec_kernel<<<(total4 + 255) / 256, 256>>>(mode_p, out, c4pv, total4);
    } else {
        roi_finalize_gen_kernel<<<(int)((total_out + 255) / 256), 256>>>(mode_p, out, C, total_out);
    }
}